// round 10
// baseline (speedup 1.0000x reference)
#include <cuda_runtime.h>
#include <cuda_fp16.h>
#include <cstdint>
#include <cstddef>

#define MDIM 16
#define KDIM 8192
#define NDIM 8192
#define KSPLIT 4
#define KPER 2048              // k per split
#define NGRP 16                // 128-k groups per split
#define NT 64                  // n tiles (128 rows each)
#define THREADS 256
#define N8W 2                  // n8 blocks per warp

// smem: frag [128 kblocks][32 lanes] uint4 (64 KB), then scratch union:
//   raw x 16 rows x 516 floats (33024 B)  OR  2 qweight stages (2 x 10240 B)
#define ROWSTRIDE 80           // 64B data + 16B pad (banks 20r%32 distinct)
#define STAGE_BYTES (128 * ROWSTRIDE)        // 10240
#define RAW_ROW 516
#define SM_FRAG 0
#define SM_SCRATCH 65536
#define SM_TOTAL (65536 + 33024)             // 98560 -> 2 CTAs/SM

__device__ __align__(16) float g_partial[KSPLIT][1024][128];   // 2 MB

__device__ __forceinline__ uint32_t smem_u32(const void* p) {
    uint32_t a;
    asm("{ .reg .u64 t; cvta.to.shared.u64 t, %1; cvt.u32.u64 %0, t; }" : "=r"(a) : "l"(p));
    return a;
}

#define CP_ASYNC16(dst, src) \
    asm volatile("cp.async.cg.shared.global [%0], [%1], 16;" \
                 :: "r"((uint32_t)(dst)), "l"(src))
#define CP_COMMIT() asm volatile("cp.async.commit_group;" ::: "memory")
#define CP_WAIT(n) asm volatile("cp.async.wait_group %0;" :: "n"(n) : "memory")

__device__ __forceinline__ void mma16816(float4& c,
                                         uint32_t a0, uint32_t a1, uint32_t a2, uint32_t a3,
                                         uint32_t b0, uint32_t b1) {
    asm volatile(
        "mma.sync.aligned.m16n8k16.row.col.f32.f16.f16.f32 "
        "{%0,%1,%2,%3},{%4,%5,%6,%7},{%8,%9},{%0,%1,%2,%3};"
        : "+f"(c.x), "+f"(c.y), "+f"(c.z), "+f"(c.w)
        : "r"(a0), "r"(a1), "r"(a2), "r"(a3), "r"(b0), "r"(b1));
}

// one int32 (8 nibbles) -> half2 {q[c], q[c+4]} * s + z  (bias removed exactly)
__device__ __forceinline__ uint32_t dq2(uint32_t w, uint32_t c4, __half2 s2, __half2 z2) {
    uint32_t t = ((w >> c4) & 0x000F000Fu) | 0x64006400u;
    uint32_t bu = 0x64006400u;
    __half2 q = __hsub2(*reinterpret_cast<__half2*>(&t), *reinterpret_cast<__half2*>(&bu));
    __half2 r = __hfma2(q, s2, z2);
    return *reinterpret_cast<uint32_t*>(&r);
}

__global__ void __launch_bounds__(THREADS, 2) wq_gemm(
    const float* __restrict__ x, const int* __restrict__ qw,
    const float* __restrict__ scales, const float* __restrict__ zeros) {
    extern __shared__ char smem[];
    uint4* frag = reinterpret_cast<uint4*>(smem + SM_FRAG);
    float* xraw = reinterpret_cast<float*>(smem + SM_SCRATCH);
    const int tid = threadIdx.x;
    const int nt = blockIdx.x & (NT - 1);
    const int ks = blockIdx.x >> 6;

    // ---- x packing: 4 sections of 512 k, coalesced raw -> frag ----
    // virtual-k permutation: 2c <-> c, 2c+1 <-> c+4
#pragma unroll 1
    for (int s = 0; s < 4; s++) {
        const float* xg = x + (size_t)ks * KPER + s * 512;
#pragma unroll
        for (int i = 0; i < 8; i++) {
            int e = tid + i * THREADS;        // 0..2047 float4 slots
            int r = e >> 7, kk = (e & 127) << 2;
            float4 v = *reinterpret_cast<const float4*>(xg + (size_t)r * KDIM + kk);
            *reinterpret_cast<float4*>(xraw + r * RAW_ROW + kk) = v;
        }
        __syncthreads();
#pragma unroll
        for (int j = 0; j < 4; j++) {
            int e = tid + j * THREADS;        // 0..1023 = (local block, lane)
            int bl = e >> 5, l = e & 31;
            int r = l >> 2, c = l & 3, kb = bl * 16;
            const float* r0 = xraw + r * RAW_ROW + kb;
            const float* r1 = xraw + (r + 8) * RAW_ROW + kb;
            __half2 a0 = __floats2half2_rn(r0[c], r0[c + 4]);
            __half2 a1 = __floats2half2_rn(r1[c], r1[c + 4]);
            __half2 a2 = __floats2half2_rn(r0[8 + c], r0[12 + c]);
            __half2 a3 = __floats2half2_rn(r1[8 + c], r1[12 + c]);
            uint4 f;
            f.x = *reinterpret_cast<uint32_t*>(&a0);
            f.y = *reinterpret_cast<uint32_t*>(&a1);
            f.z = *reinterpret_cast<uint32_t*>(&a2);
            f.w = *reinterpret_cast<uint32_t*>(&a3);
            frag[(s * 32 + bl) * 32 + l] = f;
        }
        __syncthreads();
    }

    // ---- qweight cp.async pipeline ----
    const uint32_t stage0 = smem_u32(smem + SM_SCRATCH);
    const char* qwb = reinterpret_cast<const char*>(qw) +
                      (size_t)(nt * 128) * 4096 + (size_t)ks * 1024;
#pragma unroll
    for (int gg = 0; gg < 2; gg++) {
#pragma unroll
        for (int j = 0; j < 2; j++) {
            int lin = tid + j * THREADS;      // 0..511 chunks
            int r = lin >> 2, q16 = lin & 3;
            CP_ASYNC16(stage0 + (uint32_t)gg * STAGE_BYTES + (uint32_t)(r * ROWSTRIDE + q16 * 16),
                       qwb + (size_t)r * 4096 + gg * 64 + q16 * 16);
        }
        CP_COMMIT();
    }

    // ---- main loop ----
    const int wid = tid >> 5, lane = tid & 31;
    const int nb0 = nt * 16 + wid * N8W;
    const int r_in8 = lane >> 2;
    const uint32_t c4 = (uint32_t)(lane & 3) * 4;
    const int row0 = nb0 * 8 + r_in8;
    const int lrow0 = wid * 16 + r_in8;       // CTA-local staged row

    float4 acc[N8W];
#pragma unroll
    for (int i = 0; i < N8W; i++) acc[i] = make_float4(0.f, 0.f, 0.f, 0.f);

#pragma unroll 1
    for (int g = 0; g < NGRP; g++) {
        if (g == NGRP - 1) CP_WAIT(0); else CP_WAIT(1);
        __syncthreads();

        __half2 s2[N8W], z2[N8W];
        const float* sp = scales + (size_t)(ks * NGRP + g) * NDIM + row0;
        const float* zp = zeros + (size_t)(ks * NGRP + g) * NDIM + row0;
#pragma unroll
        for (int i = 0; i < N8W; i++) {
            s2[i] = __half2half2(__float2half_rn(sp[i * 8]));
            z2[i] = __half2half2(__float2half_rn(zp[i * 8]));
        }

        const char* sbase = smem + SM_SCRATCH + (size_t)(g & 1) * STAGE_BYTES;
#pragma unroll
        for (int p = 0; p < 4; p++) {
            uint4 ah0 = frag[((g * 8 + p * 2 + 0) << 5) + lane];
            uint4 ah1 = frag[((g * 8 + p * 2 + 1) << 5) + lane];
#pragma unroll
            for (int i = 0; i < N8W; i++) {
                uint4 w = *reinterpret_cast<const uint4*>(
                    sbase + (size_t)(lrow0 + i * 8) * ROWSTRIDE + p * 16);
                uint32_t b0 = dq2(w.x, c4, s2[i], z2[i]);
                uint32_t b1 = dq2(w.y, c4, s2[i], z2[i]);
                mma16816(acc[i], ah0.x, ah0.y, ah0.z, ah0.w, b0, b1);
                b0 = dq2(w.z, c4, s2[i], z2[i]);
                b1 = dq2(w.w, c4, s2[i], z2[i]);
                mma16816(acc[i], ah1.x, ah1.y, ah1.z, ah1.w, b0, b1);
            }
        }

        __syncthreads();
        if (g + 2 < NGRP) {
            uint32_t dstbuf = stage0 + (uint32_t)(g & 1) * STAGE_BYTES;
#pragma unroll
            for (int j = 0; j < 2; j++) {
                int lin = tid + j * THREADS;
                int r = lin >> 2, q16 = lin & 3;
                CP_ASYNC16(dstbuf + (uint32_t)(r * ROWSTRIDE + q16 * 16),
                           qwb + (size_t)r * 4096 + (g + 2) * 64 + q16 * 16);
            }
            CP_COMMIT();
        }
    }

    // ---- store partials ----
    const int off = r_in8 * 8 + (lane & 3) * 2;
#pragma unroll
    for (int i = 0; i < N8W; i++) {
        float* pb = &g_partial[ks][nb0 + i][0];
        *reinterpret_cast<float2*>(pb + off) = make_float2(acc[i].x, acc[i].y);
        *reinterpret_cast<float2*>(pb + 64 + off) = make_float2(acc[i].z, acc[i].w);
    }
}

// combine: thread mapping matches partial layout -> coalesced; 4 loads in flight
__global__ void __launch_bounds__(256) wq_combine(const float* __restrict__ bias,
                                                  float* __restrict__ out) {
    int idx = blockIdx.x * 256 + threadIdx.x;   // 0..131071
    int nb = idx >> 7;                          // n8 block
    int off = idx & 127;                        // m*8 + nc
    float p0 = g_partial[0][nb][off];
    float p1 = g_partial[1][nb][off];
    float p2 = g_partial[2][nb][off];
    float p3 = g_partial[3][nb][off];
    int m = off >> 3, nc = off & 7;
    int n = nb * 8 + nc;
    out[(size_t)m * NDIM + n] = (p0 + p1) + (p2 + p3) + bias[n];
}

extern "C" void kernel_launch(void* const* d_in, const int* in_sizes, int n_in,
                              void* d_out, int out_size) {
    const float* x = (const float*)d_in[0];
    const int* qw = (const int*)d_in[1];
    const float* sc = (const float*)d_in[2];
    const float* zz = (const float*)d_in[3];
    const float* bias = (const float*)d_in[4];
    (void)in_sizes; (void)n_in; (void)out_size;

    cudaFuncSetAttribute(wq_gemm, cudaFuncAttributeMaxDynamicSharedMemorySize, SM_TOTAL);
    wq_gemm<<<NT * KSPLIT, THREADS, SM_TOTAL>>>(x, qw, sc, zz);
    wq_combine<<<(MDIM * NDIM) / 256, 256>>>(bias, (float*)d_out);
}

// round 11
// speedup vs baseline: 1.1029x; 1.1029x over previous
#include <cuda_runtime.h>
#include <cuda_fp16.h>
#include <cstdint>
#include <cstddef>

#define MDIM 16
#define KDIM 8192
#define NDIM 8192
#define KSPLIT 16
#define KPER 512               // k per split
#define NGRP 4                 // 128-k groups per split
#define NT 16                  // n tiles (512 n each)
#define THREADS 256
#define N8W 8                  // n8 blocks per warp

// smem: raw x [16][516] floats, then frags [32 blocks][32 lanes] uint4
#define RAW_ROW 516
#define SM_FRAG_OFF 33024      // 16*516*4, 16B aligned
#define SM_TOTAL (33024 + 32 * 32 * 16)   // 49408 B -> 2 CTAs/SM

__device__ __align__(16) float g_partial[KSPLIT][1024][128];   // 8 MB
__device__ int g_cnt[NT];      // arrival counters (self-resetting)
__device__ int g_done[NT];     // reduction-done counters (self-resetting)

__device__ __forceinline__ void mma16816(float4& c,
                                         uint32_t a0, uint32_t a1, uint32_t a2, uint32_t a3,
                                         uint32_t b0, uint32_t b1) {
    asm volatile(
        "mma.sync.aligned.m16n8k16.row.col.f32.f16.f16.f32 "
        "{%0,%1,%2,%3},{%4,%5,%6,%7},{%8,%9},{%0,%1,%2,%3};"
        : "+f"(c.x), "+f"(c.y), "+f"(c.z), "+f"(c.w)
        : "r"(a0), "r"(a1), "r"(a2), "r"(a3), "r"(b0), "r"(b1));
}

// one int32 (8 nibbles) -> half2 {q[c], q[c+4]} * s + z  (bias removed exactly)
__device__ __forceinline__ uint32_t dq2(uint32_t w, uint32_t c4, __half2 s2, __half2 z2) {
    uint32_t t = ((w >> c4) & 0x000F000Fu) | 0x64006400u;
    uint32_t bu = 0x64006400u;
    __half2 q = __hsub2(*reinterpret_cast<__half2*>(&t), *reinterpret_cast<__half2*>(&bu));
    __half2 r = __hfma2(q, s2, z2);
    return *reinterpret_cast<uint32_t*>(&r);
}

__global__ void __launch_bounds__(THREADS, 2) wq_gemm(
    const float* __restrict__ x, const int* __restrict__ qw,
    const float* __restrict__ scales, const float* __restrict__ zeros,
    const float* __restrict__ bias, float* __restrict__ out) {
    extern __shared__ char smem[];
    float* xraw = reinterpret_cast<float*>(smem);
    uint4* frag = reinterpret_cast<uint4*>(smem + SM_FRAG_OFF);
    const int tid = threadIdx.x;
    const int nt = blockIdx.x & (NT - 1);
    const int ks = blockIdx.x >> 4;

    // ---- phase 1: coalesced raw x chunk [16][512] -> smem (padded rows) ----
    const float* xg = x + ks * KPER;
#pragma unroll
    for (int i = 0; i < 8; i++) {
        int e = tid + i * THREADS;          // 0..2047 float4 slots
        int r = e >> 7;                     // 128 float4 per row
        int kk = (e & 127) << 2;
        float4 v = *reinterpret_cast<const float4*>(xg + (size_t)r * KDIM + kk);
        *reinterpret_cast<float4*>(xraw + r * RAW_ROW + kk) = v;
    }
    __syncthreads();

    // ---- phase 2: pack A-fragments (virtual-k permutation: 2c<->c, 2c+1<->c+4) ----
#pragma unroll
    for (int j = 0; j < 4; j++) {
        int e = tid + j * THREADS;          // 0..1023 = (block, lane)
        int b = e >> 5, l = e & 31;
        int r = l >> 2, c = l & 3, kb = b * 16;
        const float* r0 = xraw + r * RAW_ROW + kb;
        const float* r1 = xraw + (r + 8) * RAW_ROW + kb;
        __half2 a0 = __floats2half2_rn(r0[c], r0[c + 4]);
        __half2 a1 = __floats2half2_rn(r1[c], r1[c + 4]);
        __half2 a2 = __floats2half2_rn(r0[8 + c], r0[12 + c]);
        __half2 a3 = __floats2half2_rn(r1[8 + c], r1[12 + c]);
        uint4 f;
        f.x = *reinterpret_cast<uint32_t*>(&a0);
        f.y = *reinterpret_cast<uint32_t*>(&a1);
        f.z = *reinterpret_cast<uint32_t*>(&a2);
        f.w = *reinterpret_cast<uint32_t*>(&a3);
        frag[e] = f;
    }
    __syncthreads();

    // ---- main loop ----
    const int wid = tid >> 5, lane = tid & 31;
    const int nb0 = nt * 64 + wid * N8W;
    const int r_in8 = lane >> 2;
    const uint32_t c4 = (uint32_t)(lane & 3) * 4;
    const int row0 = nb0 * 8 + r_in8;

    // qweight as uint4: row stride 256; ksplit offset = 512k = 64 int32 = 16 uint4
    const uint4* qp = reinterpret_cast<const uint4*>(qw) + (size_t)row0 * 256 + ks * 16;

    float4 acc[N8W];
#pragma unroll
    for (int i = 0; i < N8W; i++) acc[i] = make_float4(0.f, 0.f, 0.f, 0.f);

#pragma unroll 1
    for (int g = 0; g < NGRP; g++) {
        __half2 s2[N8W], z2[N8W];
        const float* sp = scales + (size_t)(ks * NGRP + g) * NDIM + row0;
        const float* zp = zeros + (size_t)(ks * NGRP + g) * NDIM + row0;
#pragma unroll
        for (int i = 0; i < N8W; i++) {
            s2[i] = __half2half2(__float2half_rn(sp[i * 8]));
            z2[i] = __half2half2(__float2half_rn(zp[i * 8]));
        }
#pragma unroll
        for (int p = 0; p < 4; p++) {       // 4 uint4 = 8 k16-blocks per group-row
            uint4 wq[N8W];
#pragma unroll
            for (int i = 0; i < N8W; i++)
                wq[i] = qp[(size_t)i * 2048 + g * 4 + p];
#pragma unroll
            for (int sub = 0; sub < 2; sub++) {
                uint4 ah = frag[((g * 8 + p * 2 + sub) << 5) + lane];
#pragma unroll
                for (int i = 0; i < N8W; i++) {
                    uint32_t w0 = sub ? wq[i].z : wq[i].x;
                    uint32_t w1 = sub ? wq[i].w : wq[i].y;
                    uint32_t b0 = dq2(w0, c4, s2[i], z2[i]);
                    uint32_t b1 = dq2(w1, c4, s2[i], z2[i]);
                    mma16816(acc[i], ah.x, ah.y, ah.z, ah.w, b0, b1);
                }
            }
        }
    }

    // ---- store partials ----
    const int off = r_in8 * 8 + (lane & 3) * 2;
#pragma unroll
    for (int i = 0; i < N8W; i++) {
        float* pb = &g_partial[ks][nb0 + i][0];
        *reinterpret_cast<float2*>(pb + off) = make_float2(acc[i].x, acc[i].y);
        *reinterpret_cast<float2*>(pb + 64 + off) = make_float2(acc[i].z, acc[i].w);
    }

    // ---- fused split-K reduction (threadfence-reduction pattern) ----
    __threadfence();
    __syncthreads();
    if (tid == 0) atomicAdd(&g_cnt[nt], 1);

    // wait for all 16 ks-CTAs of this tile
    if (tid == 0) {
        int v;
        do {
            asm volatile("ld.acquire.gpu.b32 %0, [%1];" : "=r"(v) : "l"(&g_cnt[nt]));
            if (v < KSPLIT) __nanosleep(64);
        } while (v < KSPLIT);
    }
    __syncthreads();

    // this CTA reduces chunk ks of tile nt: 512 outputs, 2 per thread
#pragma unroll
    for (int u = 0; u < 2; u++) {
        int t = ks * 512 + tid + u * 256;        // 0..8191 within tile
        int nbl = t >> 7, o = t & 127;
        int nb = nt * 64 + nbl;
        float s = 0.f;
#pragma unroll
        for (int k2 = 0; k2 < KSPLIT; k2++) s += g_partial[k2][nb][o];
        int m = o >> 3, n = nb * 8 + (o & 7);
        out[(size_t)m * NDIM + n] = s + bias[n];
    }

    // ---- self-reset counters for graph replay ----
    __syncthreads();
    if (tid == 0) {
        int old = atomicAdd(&g_done[nt], 1);
        if (old == KSPLIT - 1) {
            atomicExch(&g_cnt[nt], 0);
            atomicExch(&g_done[nt], 0);
        }
    }
}

extern "C" void kernel_launch(void* const* d_in, const int* in_sizes, int n_in,
                              void* d_out, int out_size) {
    const float* x = (const float*)d_in[0];
    const int* qw = (const int*)d_in[1];
    const float* sc = (const float*)d_in[2];
    const float* zz = (const float*)d_in[3];
    const float* bias = (const float*)d_in[4];
    (void)in_sizes; (void)n_in; (void)out_size;

    cudaFuncSetAttribute(wq_gemm, cudaFuncAttributeMaxDynamicSharedMemorySize, SM_TOTAL);
    wq_gemm<<<NT * KSPLIT, THREADS, SM_TOTAL>>>(x, qw, sc, zz, bias, (float*)d_out);
}